// round 2
// baseline (speedup 1.0000x reference)
#include <cuda_runtime.h>
#include <cuda_bf16.h>
#include <cstdint>

// Problem constants (fixed by the reference)
#define N_NODES_MAX 100000
#define FEAT 16

// Scratch: degree histogram + precomputed per-node output row
__device__ int   g_deg[N_NODES_MAX];
__device__ float g_y[N_NODES_MAX * FEAT];

// ---------------------------------------------------------------------------
// Kernel 1: zero the degree histogram
// ---------------------------------------------------------------------------
__global__ void zero_deg_kernel(int n) {
    int i = blockIdx.x * blockDim.x + threadIdx.x;
    if (i < n) g_deg[i] = 0;
}

// ---------------------------------------------------------------------------
// Kernel 2: degree histogram over src = edge_index[0]  (int32 indices!)
// Vectorized int4 loads: 4 indices per thread, spread atomics.
// ---------------------------------------------------------------------------
__global__ void hist_kernel(const int4* __restrict__ src4, int E4) {
    int i = blockIdx.x * blockDim.x + threadIdx.x;
    if (i < E4) {
        int4 s = src4[i];
        atomicAdd(&g_deg[s.x], 1);
        atomicAdd(&g_deg[s.y], 1);
        atomicAdd(&g_deg[s.z], 1);
        atomicAdd(&g_deg[s.w], 1);
    }
}

// ---------------------------------------------------------------------------
// Kernel 3: per-node precompute  y[n] = (deg[n]-1) * x[n] + extra[n]
// One thread per (node, float4-chunk): n4 = N * 4 threads.
// ---------------------------------------------------------------------------
__global__ void compute_y_kernel(const float4* __restrict__ x4,
                                 const float4* __restrict__ e4,
                                 int n4) {
    int i = blockIdx.x * blockDim.x + threadIdx.x;
    if (i < n4) {
        int node = i >> 2;                  // FEAT/4 = 4 chunks per node
        float s = (float)(g_deg[node] - 1);
        float4 xv = x4[i];
        float4 ev = e4[i];
        float4 y;
        y.x = fmaf(s, xv.x, ev.x);
        y.y = fmaf(s, xv.y, ev.y);
        y.z = fmaf(s, xv.z, ev.z);
        y.w = fmaf(s, xv.w, ev.w);
        reinterpret_cast<float4*>(g_y)[i] = y;
    }
}

// ---------------------------------------------------------------------------
// Kernel 4: edge gather  out[e] = y[src[e]]
// 4 threads per edge, each moves one float4 (16B).  Stores fully coalesced;
// the 4 gather loads of one edge hit the same 64B of a row (L2-resident y).
// ---------------------------------------------------------------------------
__global__ void gather_kernel(const int* __restrict__ src,
                              float4* __restrict__ out4,
                              int total /* = E*4 */) {
    int t = blockIdx.x * blockDim.x + threadIdx.x;
    if (t < total) {
        int e  = t >> 2;
        int f4 = t & 3;
        int s = src[e];
        float4 v = reinterpret_cast<const float4*>(g_y)[s * 4 + f4];
        out4[t] = v;
    }
}

// ---------------------------------------------------------------------------
extern "C" void kernel_launch(void* const* d_in, const int* in_sizes, int n_in,
                              void* d_out, int out_size) {
    const float* x     = (const float*)d_in[0];       // [N, 16] f32
    const float* extra = (const float*)d_in[1];       // [N, 16] f32
    const int* edge_index = (const int*)d_in[2];      // [2, E] int32 row-major

    int N = in_sizes[0] / FEAT;
    int E = in_sizes[2] / 2;
    const int* src = edge_index;                      // row 0 = edge_index[0]

    const int B = 256;

    // 1) zero degrees
    zero_deg_kernel<<<(N + B - 1) / B, B>>>(N);

    // 2) histogram (E is 3.2M, divisible by 4)
    int E4 = E / 4;
    hist_kernel<<<(E4 + B - 1) / B, B>>>((const int4*)src, E4);

    // 3) per-node y = (deg-1)*x + extra
    int n4 = N * (FEAT / 4);
    compute_y_kernel<<<(n4 + B - 1) / B, B>>>(
        (const float4*)x, (const float4*)extra, n4);

    // 4) gather to output
    int total = E * 4;
    gather_kernel<<<(total + B - 1) / B, B>>>(src, (float4*)d_out, total);
}

// round 3
// speedup vs baseline: 1.1227x; 1.1227x over previous
#include <cuda_runtime.h>
#include <cuda_bf16.h>
#include <cstdint>

#define N_NODES_MAX 100000
#define FEAT 16

__device__ int   g_deg[N_NODES_MAX];
__device__ float g_y[N_NODES_MAX * FEAT];

// ---------------------------------------------------------------------------
// Kernel 1: zero the degree histogram
// ---------------------------------------------------------------------------
__global__ void zero_deg_kernel(int n) {
    int i = blockIdx.x * blockDim.x + threadIdx.x;
    if (i < n) g_deg[i] = 0;
}

// ---------------------------------------------------------------------------
// Kernel 2: degree histogram. 8 indices per thread (2x int4 loads),
// atomics are fire-and-forget -> compiler emits REDG (no return).
// ---------------------------------------------------------------------------
__global__ void hist_kernel(const int4* __restrict__ src4, int E8 /* = E/8 */) {
    int i = blockIdx.x * blockDim.x + threadIdx.x;
    if (i < E8) {
        int4 a = src4[2 * i];
        int4 b = src4[2 * i + 1];
        atomicAdd(&g_deg[a.x], 1);
        atomicAdd(&g_deg[a.y], 1);
        atomicAdd(&g_deg[a.z], 1);
        atomicAdd(&g_deg[a.w], 1);
        atomicAdd(&g_deg[b.x], 1);
        atomicAdd(&g_deg[b.y], 1);
        atomicAdd(&g_deg[b.z], 1);
        atomicAdd(&g_deg[b.w], 1);
    }
}

// ---------------------------------------------------------------------------
// Kernel 3: per-node precompute  y[n] = (deg[n]-1) * x[n] + extra[n]
// ---------------------------------------------------------------------------
__global__ void compute_y_kernel(const float4* __restrict__ x4,
                                 const float4* __restrict__ e4,
                                 int n4) {
    int i = blockIdx.x * blockDim.x + threadIdx.x;
    if (i < n4) {
        int node = i >> 2;
        float s = (float)(g_deg[node] - 1);
        float4 xv = x4[i];
        float4 ev = e4[i];
        float4 y;
        y.x = fmaf(s, xv.x, ev.x);
        y.y = fmaf(s, xv.y, ev.y);
        y.z = fmaf(s, xv.z, ev.z);
        y.w = fmaf(s, xv.w, ev.w);
        reinterpret_cast<float4*>(g_y)[i] = y;
    }
}

// ---------------------------------------------------------------------------
// Kernel 4: edge gather  out[e] = y[src[e]]  with ILP=4.
// Each thread owns 4 independent elements {t, t+Q, t+2Q, t+3Q} where
// Q = total/4. All 4 src loads issue back-to-back, then all 4 gather
// loads, then 4 stores -> MLP=4 per thread, all accesses coalesced.
// ---------------------------------------------------------------------------
__global__ void gather_kernel(const int* __restrict__ src,
                              float4* __restrict__ out4,
                              int Q /* = E*4/4 = E */) {
    int t = blockIdx.x * blockDim.x + threadIdx.x;
    if (t < Q) {
        const float4* __restrict__ y4 = reinterpret_cast<const float4*>(g_y);

        int s0, s1, s2, s3;
        {
            int i0 = t;
            int i1 = t + Q;
            int i2 = t + 2 * Q;
            int i3 = t + 3 * Q;
            s0 = __ldg(&src[i0 >> 2]);
            s1 = __ldg(&src[i1 >> 2]);
            s2 = __ldg(&src[i2 >> 2]);
            s3 = __ldg(&src[i3 >> 2]);

            float4 v0 = __ldg(&y4[s0 * 4 + (i0 & 3)]);
            float4 v1 = __ldg(&y4[s1 * 4 + (i1 & 3)]);
            float4 v2 = __ldg(&y4[s2 * 4 + (i2 & 3)]);
            float4 v3 = __ldg(&y4[s3 * 4 + (i3 & 3)]);

            out4[i0] = v0;
            out4[i1] = v1;
            out4[i2] = v2;
            out4[i3] = v3;
        }
    }
}

// ---------------------------------------------------------------------------
extern "C" void kernel_launch(void* const* d_in, const int* in_sizes, int n_in,
                              void* d_out, int out_size) {
    const float* x     = (const float*)d_in[0];       // [N, 16] f32
    const float* extra = (const float*)d_in[1];       // [N, 16] f32
    const int* edge_index = (const int*)d_in[2];      // [2, E] int32 row-major

    int N = in_sizes[0] / FEAT;
    int E = in_sizes[2] / 2;
    const int* src = edge_index;                      // row 0 = edge_index[0]

    const int B = 256;

    // 1) zero degrees
    zero_deg_kernel<<<(N + B - 1) / B, B>>>(N);

    // 2) histogram (E = 3.2M, divisible by 8)
    int E8 = E / 8;
    hist_kernel<<<(E8 + B - 1) / B, B>>>((const int4*)src, E8);

    // 3) per-node y = (deg-1)*x + extra
    int n4 = N * (FEAT / 4);
    compute_y_kernel<<<(n4 + B - 1) / B, B>>>(
        (const float4*)x, (const float4*)extra, n4);

    // 4) gather: total = E*4 float4 elements, ILP=4 -> Q = E threads
    int Q = E;  // (E*4)/4
    gather_kernel<<<(Q + B - 1) / B, B>>>(src, (float4*)d_out, Q);
}

// round 4
// speedup vs baseline: 1.1530x; 1.0270x over previous
#include <cuda_runtime.h>
#include <cuda_bf16.h>
#include <cstdint>

#define N_NODES_MAX 100000
#define FEAT 16

__device__ int   g_deg[N_NODES_MAX];
__device__ float g_y[N_NODES_MAX * FEAT];

// ---------------------------------------------------------------------------
// Kernel 1: zero the degree histogram
// ---------------------------------------------------------------------------
__global__ void zero_deg_kernel(int n4) {
    int i = blockIdx.x * blockDim.x + threadIdx.x;
    if (i < n4) reinterpret_cast<int4*>(g_deg)[i] = make_int4(0, 0, 0, 0);
}

// ---------------------------------------------------------------------------
// Kernel 2: degree histogram. 16 indices per thread (4x int4 loads),
// fire-and-forget atomics -> REDG (no return value).
// ---------------------------------------------------------------------------
__global__ void hist_kernel(const int4* __restrict__ src4, int E16 /* = E/16 */) {
    int i = blockIdx.x * blockDim.x + threadIdx.x;
    if (i < E16) {
        int4 a = src4[4 * i];
        int4 b = src4[4 * i + 1];
        int4 c = src4[4 * i + 2];
        int4 d = src4[4 * i + 3];
        atomicAdd(&g_deg[a.x], 1); atomicAdd(&g_deg[a.y], 1);
        atomicAdd(&g_deg[a.z], 1); atomicAdd(&g_deg[a.w], 1);
        atomicAdd(&g_deg[b.x], 1); atomicAdd(&g_deg[b.y], 1);
        atomicAdd(&g_deg[b.z], 1); atomicAdd(&g_deg[b.w], 1);
        atomicAdd(&g_deg[c.x], 1); atomicAdd(&g_deg[c.y], 1);
        atomicAdd(&g_deg[c.z], 1); atomicAdd(&g_deg[c.w], 1);
        atomicAdd(&g_deg[d.x], 1); atomicAdd(&g_deg[d.y], 1);
        atomicAdd(&g_deg[d.z], 1); atomicAdd(&g_deg[d.w], 1);
    }
}

// ---------------------------------------------------------------------------
// Kernel 3: per-node precompute  y[n] = (deg[n]-1) * x[n] + extra[n]
// ---------------------------------------------------------------------------
__global__ void compute_y_kernel(const float4* __restrict__ x4,
                                 const float4* __restrict__ e4,
                                 int n4) {
    int i = blockIdx.x * blockDim.x + threadIdx.x;
    if (i < n4) {
        int node = i >> 2;
        float s = (float)(g_deg[node] - 1);
        float4 xv = x4[i];
        float4 ev = e4[i];
        float4 y;
        y.x = fmaf(s, xv.x, ev.x);
        y.y = fmaf(s, xv.y, ev.y);
        y.z = fmaf(s, xv.z, ev.z);
        y.w = fmaf(s, xv.w, ev.w);
        reinterpret_cast<float4*>(g_y)[i] = y;
    }
}

// ---------------------------------------------------------------------------
// Kernel 4: edge gather  out[e*4+f] = y[src[e]*4+f]  with ILP=8.
// Thread t owns elements {t + k*Q : k=0..7}, Q = total/8. Batch-issues
// 8 src loads, 8 gather loads, 8 streaming stores -> MLP=8, all coalesced.
// ---------------------------------------------------------------------------
__global__ void __launch_bounds__(256) gather_kernel(
        const int* __restrict__ src,
        float4* __restrict__ out4,
        int Q /* = E*4/8 */) {
    int t = blockIdx.x * blockDim.x + threadIdx.x;
    if (t < Q) {
        const float4* __restrict__ y4 = reinterpret_cast<const float4*>(g_y);

        int idx[8];
        int s[8];
        float4 v[8];
#pragma unroll
        for (int k = 0; k < 8; k++) idx[k] = t + k * Q;
#pragma unroll
        for (int k = 0; k < 8; k++) s[k] = __ldg(&src[idx[k] >> 2]);
#pragma unroll
        for (int k = 0; k < 8; k++) v[k] = __ldg(&y4[s[k] * 4 + (idx[k] & 3)]);
#pragma unroll
        for (int k = 0; k < 8; k++) __stcs(&out4[idx[k]], v[k]);
    }
}

// ---------------------------------------------------------------------------
extern "C" void kernel_launch(void* const* d_in, const int* in_sizes, int n_in,
                              void* d_out, int out_size) {
    const float* x     = (const float*)d_in[0];       // [N, 16] f32
    const float* extra = (const float*)d_in[1];       // [N, 16] f32
    const int* edge_index = (const int*)d_in[2];      // [2, E] int32 row-major

    int N = in_sizes[0] / FEAT;
    int E = in_sizes[2] / 2;
    const int* src = edge_index;                      // row 0 = edge_index[0]

    const int B = 256;

    // 1) zero degrees (N = 100000 divisible by 4)
    int z4 = N / 4;
    zero_deg_kernel<<<(z4 + B - 1) / B, B>>>(z4);

    // 2) histogram (E = 3.2M, divisible by 16)
    int E16 = E / 16;
    hist_kernel<<<(E16 + B - 1) / B, B>>>((const int4*)src, E16);

    // 3) per-node y = (deg-1)*x + extra
    int n4 = N * (FEAT / 4);
    compute_y_kernel<<<(n4 + B - 1) / B, B>>>(
        (const float4*)x, (const float4*)extra, n4);

    // 4) gather: total = E*4 float4 elements, ILP=8 -> Q = E/2 threads
    int Q = E / 2;  // (E*4)/8
    gather_kernel<<<(Q + B - 1) / B, B>>>(src, (float4*)d_out, Q);
}